// round 1
// baseline (speedup 1.0000x reference)
#include <cuda_runtime.h>

#define BB 64
#define NN 4096
#define DD 64
#define SS 7

// ---------------- scratch (static device globals; no allocation) ----------------
__device__ float g_k[BB * NN * DD];          // 64 MB
__device__ float g_v[BB * NN * DD];          // 64 MB
__device__ float g_qT[BB * DD * 8];          // q transposed [b][d][s] (pad 8)
__device__ float g_slots[BB * SS * DD];
__device__ float g_numer[BB * SS * DD];
__device__ float g_denom[BB * SS];

// ---------------- packed fp32x2 helpers (sm_100+) ----------------
__device__ __forceinline__ unsigned long long pk2(float a, float b) {
    unsigned long long r;
    asm("mov.b64 %0, {%1, %2};" : "=l"(r) : "f"(a), "f"(b));
    return r;
}
__device__ __forceinline__ void fma2(unsigned long long& d, unsigned long long a, unsigned long long b) {
    asm("fma.rn.f32x2 %0, %1, %2, %0;" : "+l"(d) : "l"(a), "l"(b));
}
__device__ __forceinline__ float2 upk2(unsigned long long v) {
    float2 r;
    asm("mov.b64 {%0, %1}, %2;" : "=f"(r.x), "=f"(r.y) : "l"(v));
    return r;
}

// ---------------- kernel 1: LN(x), k = xn@Wk, v = xn@Wv ----------------
// grid: BN/64 blocks, 256 threads. Tile: 64 rows x 64 cols, two phases (Wk, Wv).
__global__ __launch_bounds__(256) void proj_kernel(
    const float* __restrict__ x,
    const float* __restrict__ lg, const float* __restrict__ lb,
    const float* __restrict__ Wk, const float* __restrict__ Wv)
{
    __shared__ float sA[64 * 68];   // padded pitch 68 (16B-aligned rows, low-conflict)
    __shared__ float sW[64 * 64];
    const int tid = threadIdx.x;
    const int row0 = blockIdx.x * 64;

    // load x tile (64 rows x 64 floats) coalesced as float4
    const float4* x4 = (const float4*)(x + (size_t)row0 * 64);
#pragma unroll
    for (int t = 0; t < 4; t++) {
        int F = t * 256 + tid;                 // float4 index within tile
        float4 vv = x4[F];
        *(float4*)&sA[(F >> 4) * 68 + (F & 15) * 4] = vv;
    }
    __syncthreads();

    // layernorm rows in place: 8 warps x 8 rows, 2 elems/lane
    {
        int w = tid >> 5, l = tid & 31;
        float g0 = lg[2 * l], g1 = lg[2 * l + 1];
        float b0 = lb[2 * l], b1 = lb[2 * l + 1];
#pragma unroll
        for (int rr = 0; rr < 8; rr++) {
            int r = w * 8 + rr;
            float a0 = sA[r * 68 + 2 * l], a1 = sA[r * 68 + 2 * l + 1];
            float s = a0 + a1, s2 = a0 * a0 + a1 * a1;
#pragma unroll
            for (int o = 16; o; o >>= 1) {
                s  += __shfl_xor_sync(0xffffffffu, s, o);
                s2 += __shfl_xor_sync(0xffffffffu, s2, o);
            }
            float m = s * 0.015625f;
            float var = fmaxf(s2 * 0.015625f - m * m, 0.f);
            float inv = rsqrtf(var + 1e-5f);
            sA[r * 68 + 2 * l]     = (a0 - m) * inv * g0 + b0;
            sA[r * 68 + 2 * l + 1] = (a1 - m) * inv * g1 + b1;
        }
    }

    const int ty = tid >> 4, tx = tid & 15;    // 16x16: 4 rows x 4 cols per thread
#pragma unroll
    for (int ph = 0; ph < 2; ph++) {
        const float* W = ph ? Wv : Wk;
        __syncthreads();
#pragma unroll
        for (int t = 0; t < 4; t++) {
            int F = t * 256 + tid;
            ((float4*)sW)[F] = ((const float4*)W)[F];
        }
        __syncthreads();

        unsigned long long acc[8];
#pragma unroll
        for (int j = 0; j < 8; j++) acc[j] = pk2(0.f, 0.f);

#pragma unroll 8
        for (int i = 0; i < 64; i++) {
            float4 b4 = *(float4*)&sW[i * 64 + tx * 4];
            unsigned long long b01 = pk2(b4.x, b4.y);
            unsigned long long b23 = pk2(b4.z, b4.w);
#pragma unroll
            for (int j = 0; j < 4; j++) {
                float a = sA[(ty * 4 + j) * 68 + i];
                unsigned long long aa = pk2(a, a);
                fma2(acc[j * 2 + 0], aa, b01);
                fma2(acc[j * 2 + 1], aa, b23);
            }
        }

        float* out = ph ? g_v : g_k;
#pragma unroll
        for (int j = 0; j < 4; j++) {
            float2 lo = upk2(acc[j * 2]), hi = upk2(acc[j * 2 + 1]);
            float4 o4 = make_float4(lo.x, lo.y, hi.x, hi.y);
            *(float4*)&out[(size_t)(row0 + ty * 4 + j) * 64 + tx * 4] = o4;
        }
    }
}

// ---------------- kernel 2: broadcast slots_init ----------------
__global__ void init_slots_kernel(const float* __restrict__ s0) {
    int i = blockIdx.x * blockDim.x + threadIdx.x;
    if (i < BB * SS * DD) g_slots[i] = s0[i % (SS * DD)];
}

// ---------------- kernel 3: LN(slots), q = sn@Wq * scale; zero accumulators ----
// grid: B*S blocks of 64 threads (thread = d)
__global__ __launch_bounds__(64) void q_kernel(
    const float* __restrict__ lg, const float* __restrict__ lb,
    const float* __restrict__ Wq)
{
    const int blk = blockIdx.x;           // b*7 + s
    const int b = blk / SS, s = blk % SS;
    const int d = threadIdx.x;
    const int lane = d & 31, wid = d >> 5;

    float v = g_slots[blk * 64 + d];
    float s1 = v, s2 = v * v;
#pragma unroll
    for (int o = 16; o; o >>= 1) {
        s1 += __shfl_xor_sync(0xffffffffu, s1, o);
        s2 += __shfl_xor_sync(0xffffffffu, s2, o);
    }
    __shared__ float red[4];
    if (lane == 0) { red[wid] = s1; red[2 + wid] = s2; }
    __syncthreads();
    float S = red[0] + red[1], S2 = red[2] + red[3];
    float m = S * 0.015625f;
    float var = fmaxf(S2 * 0.015625f - m * m, 0.f);
    float inv = rsqrtf(var + 1e-5f);
    float sn = (v - m) * inv * lg[d] + lb[d];

    __shared__ float ssn[64];
    ssn[d] = sn;
    __syncthreads();

    float q = 0.f;
#pragma unroll 8
    for (int j = 0; j < 64; j++) q += ssn[j] * Wq[j * 64 + d];
    q *= 0.125f;                          // 1/sqrt(DP)

    g_qT[b * 512 + d * 8 + s] = q;
    if (s == 0) g_qT[b * 512 + d * 8 + 7] = 0.f;   // pad slot
    g_numer[blk * 64 + d] = 0.f;
    if (d == 0) g_denom[blk] = 0.f;
}

// ---------------- kernel 4: attention pass (the heavy one) ----------------
// grid: (8 tiles, B), 128 threads = 4 warps. Each warp: 4 chunks of 32 rows.
__global__ __launch_bounds__(128) void attn_kernel() {
    const int b = blockIdx.y, tile = blockIdx.x;
    const int w = threadIdx.x >> 5, lane = threadIdx.x & 31;

    __shared__ float sQT[64 * 8];        // q transposed [d][s] (pad 8)
    __shared__ float sK[4][32 * 65];     // per-warp k tile, pitch 65 (conflict-free)
    __shared__ float sw_[4][32 * 9];     // per-warp softmax weights, pitch 9

#pragma unroll
    for (int t = 0; t < 4; t++)
        sQT[t * 128 + threadIdx.x] = g_qT[b * 512 + t * 128 + threadIdx.x];
    __syncthreads();

    float nacc[14];
    float dacc[7];
#pragma unroll
    for (int i = 0; i < 14; i++) nacc[i] = 0.f;
#pragma unroll
    for (int i = 0; i < 7; i++) dacc[i] = 0.f;

    const size_t rowbase = (size_t)b * NN + tile * 512 + w * 128;
    float* myK = sK[w];
    float* myW = sw_[w];

    for (int ch = 0; ch < 4; ch++) {
        // stage 32 k rows into smem (coalesced global reads)
        const float* kk = g_k + (rowbase + ch * 32) * 64;
#pragma unroll 8
        for (int r = 0; r < 32; r++) {
            myK[r * 65 + lane]      = kk[r * 64 + lane];
            myK[r * 65 + 32 + lane] = kk[r * 64 + 32 + lane];
        }
        __syncwarp();

        // phase 1: lane = row. 7 logits per row via broadcast q reads.
        float p0 = 0, p1 = 0, p2 = 0, p3 = 0, p4 = 0, p5 = 0, p6 = 0;
        const float* krow = myK + lane * 65;
#pragma unroll 8
        for (int d = 0; d < 64; d++) {
            float kd = krow[d];
            float4 q0 = *(float4*)&sQT[d * 8];
            float4 q1 = *(float4*)&sQT[d * 8 + 4];
            p0 += kd * q0.x; p1 += kd * q0.y; p2 += kd * q0.z; p3 += kd * q0.w;
            p4 += kd * q1.x; p5 += kd * q1.y; p6 += kd * q1.z;
        }
        // softmax over 7 slots + EPS_ATTN
        float mx = fmaxf(fmaxf(fmaxf(p0, p1), fmaxf(p2, p3)),
                         fmaxf(fmaxf(p4, p5), p6));
        float e0 = __expf(p0 - mx), e1 = __expf(p1 - mx), e2 = __expf(p2 - mx);
        float e3 = __expf(p3 - mx), e4 = __expf(p4 - mx), e5 = __expf(p5 - mx);
        float e6 = __expf(p6 - mx);
        float sum = e0 + e1 + e2 + e3 + e4 + e5 + e6;
        float inv = 1.f / sum;
        float* wr = myW + lane * 9;
        wr[0] = e0 * inv + 1e-8f; wr[1] = e1 * inv + 1e-8f;
        wr[2] = e2 * inv + 1e-8f; wr[3] = e3 * inv + 1e-8f;
        wr[4] = e4 * inv + 1e-8f; wr[5] = e5 * inv + 1e-8f;
        wr[6] = e6 * inv + 1e-8f;
        __syncwarp();

        // phase 2: lane = channel pair. accumulate numer/denom over rows.
        const float* vv = g_v + (rowbase + ch * 32) * 64;
#pragma unroll 4
        for (int r = 0; r < 32; r++) {
            float2 v2 = *(const float2*)&vv[r * 64 + lane * 2];
            const float* ww = myW + r * 9;
#pragma unroll
            for (int s = 0; s < 7; s++) {
                float ws = ww[s];
                nacc[2 * s]     += ws * v2.x;
                nacc[2 * s + 1] += ws * v2.y;
                dacc[s]         += ws;
            }
        }
        __syncwarp();
    }

    // fold into global accumulators (32 warps per b -> low contention)
    float* np = g_numer + b * (SS * DD);
#pragma unroll
    for (int s = 0; s < 7; s++) {
        atomicAdd(&np[s * 64 + 2 * lane],     nacc[2 * s]);
        atomicAdd(&np[s * 64 + 2 * lane + 1], nacc[2 * s + 1]);
    }
    if (lane == 0) {
#pragma unroll
        for (int s = 0; s < 7; s++) atomicAdd(&g_denom[b * SS + s], dacc[s]);
    }
}

// ---------------- kernel 5: updates -> GRU -> MLP -> slots ----------------
// grid: B*S blocks of 64 threads (thread = d)
__global__ __launch_bounds__(64) void update_kernel(
    const float* __restrict__ wih, const float* __restrict__ whh,
    const float* __restrict__ bih, const float* __restrict__ bhh,
    const float* __restrict__ w1,  const float* __restrict__ b1v,
    const float* __restrict__ w2,  const float* __restrict__ b2v,
    float* __restrict__ out)
{
    const int blk = blockIdx.x;
    const int d = threadIdx.x;
    __shared__ float su[64], sh[64], shn[64], smm[128];
    __shared__ float sWi[64 * 65], sWh[64 * 65];

    float den = g_denom[blk];
    float u = g_numer[blk * 64 + d] / den;
    float h = g_slots[blk * 64 + d];
    su[d] = u; sh[d] = h;

    float gi[3], gh[3];
    for (int gate = 0; gate < 3; gate++) {
        __syncthreads();
        // stage both gate matrices coalesced into padded smem
#pragma unroll 8
        for (int t = 0; t < 64; t++) {
            int f = t * 64 + d;
            sWi[t * 65 + d] = wih[gate * 4096 + f];
            sWh[t * 65 + d] = whh[gate * 4096 + f];
        }
        __syncthreads();
        float a = bih[gate * 64 + d], c = bhh[gate * 64 + d];
#pragma unroll 8
        for (int t = 0; t < 64; t++) {
            a += su[t] * sWi[d * 65 + t];
            c += sh[t] * sWh[d * 65 + t];
        }
        gi[gate] = a; gh[gate] = c;
    }

    float r = 1.f / (1.f + __expf(-(gi[0] + gh[0])));
    float z = 1.f / (1.f + __expf(-(gi[1] + gh[1])));
    float n = tanhf(gi[2] + r * gh[2]);
    float hn = (1.f - z) * n + z * h;

    __syncthreads();
    shn[d] = hn;
    __syncthreads();

    float m0 = b1v[d], m1 = b1v[64 + d];
#pragma unroll 8
    for (int t = 0; t < 64; t++) {
        float ht = shn[t];
        m0 += ht * w1[t * 128 + d];
        m1 += ht * w1[t * 128 + 64 + d];
    }
    smm[d] = fmaxf(m0, 0.f);
    smm[64 + d] = fmaxf(m1, 0.f);
    __syncthreads();

    float o = hn + b2v[d];
#pragma unroll 8
    for (int c = 0; c < 128; c++) o += smm[c] * w2[c * 64 + d];

    g_slots[blk * 64 + d] = o;
    if (out) out[blk * 64 + d] = o;
}

// ---------------- launch ----------------
extern "C" void kernel_launch(void* const* d_in, const int* in_sizes, int n_in,
                              void* d_out, int out_size) {
    (void)in_sizes; (void)n_in; (void)out_size;
    const float* x          = (const float*)d_in[0];
    const float* ln_inp_g   = (const float*)d_in[1];
    const float* ln_inp_b   = (const float*)d_in[2];
    const float* ln_slot_g  = (const float*)d_in[3];
    const float* ln_slot_b  = (const float*)d_in[4];
    const float* slots_init = (const float*)d_in[5];
    const float* Wk         = (const float*)d_in[6];
    const float* Wv         = (const float*)d_in[7];
    const float* Wq         = (const float*)d_in[8];
    const float* gwih       = (const float*)d_in[9];
    const float* gwhh       = (const float*)d_in[10];
    const float* gbih       = (const float*)d_in[11];
    const float* gbhh       = (const float*)d_in[12];
    const float* w1         = (const float*)d_in[13];
    const float* b1         = (const float*)d_in[14];
    const float* w2         = (const float*)d_in[15];
    const float* b2         = (const float*)d_in[16];
    float* out = (float*)d_out;

    proj_kernel<<<(BB * NN) / 64, 256>>>(x, ln_inp_g, ln_inp_b, Wk, Wv);
    init_slots_kernel<<<(BB * SS * DD + 255) / 256, 256>>>(slots_init);
    for (int it = 0; it < 3; it++) {
        q_kernel<<<BB * SS, 64>>>(ln_slot_g, ln_slot_b, Wq);
        attn_kernel<<<dim3(8, BB), 128>>>();
        update_kernel<<<BB * SS, 64>>>(gwih, gwhh, gbih, gbhh,
                                       w1, b1, w2, b2, it == 2 ? out : nullptr);
    }
}

// round 2
// speedup vs baseline: 1.4312x; 1.4312x over previous
#include <cuda_runtime.h>

#define BB 64
#define NN 4096
#define DD 64
#define SS 7

// ---------------- scratch (static device globals; no allocation) ----------------
__device__ unsigned g_k[BB * NN * 32];       // bf16x2 words: 32 MB
__device__ unsigned g_v[BB * NN * 32];       // 32 MB
__device__ float g_qT[BB * DD * 8];          // q transposed [b][d][s] (pad 8)
__device__ float g_slots[BB * SS * DD];
__device__ float g_numer[BB * SS * DD];
__device__ float g_denom[BB * SS];

// ---------------- packed helpers ----------------
__device__ __forceinline__ unsigned long long pk2(float a, float b) {
    unsigned long long r;
    asm("mov.b64 %0, {%1, %2};" : "=l"(r) : "f"(a), "f"(b));
    return r;
}
__device__ __forceinline__ void fma2(unsigned long long& d, unsigned long long a, unsigned long long b) {
    asm("fma.rn.f32x2 %0, %1, %2, %0;" : "+l"(d) : "l"(a), "l"(b));
}
__device__ __forceinline__ float2 upk2(unsigned long long v) {
    float2 r;
    asm("mov.b64 {%0, %1}, %2;" : "=f"(r.x), "=f"(r.y) : "l"(v));
    return r;
}
__device__ __forceinline__ unsigned bf2(float lo, float hi) {
    unsigned r;
    asm("cvt.rn.bf16x2.f32 %0, %1, %2;" : "=r"(r) : "f"(hi), "f"(lo));
    return r;
}
__device__ __forceinline__ float bflo(unsigned w) { return __uint_as_float(w << 16); }
__device__ __forceinline__ float bfhi(unsigned w) { return __uint_as_float(w & 0xffff0000u); }
__device__ __forceinline__ unsigned long long bfpair(unsigned w) {
    return pk2(bflo(w), bfhi(w));
}

// ---------------- kernel 1: LN(x), [k|v] = xn @ [Wk|Wv], bf16 out --------------
// grid: BN/64 blocks, 128 threads. Tile 64 rows x 128 cols, 8x8 per thread.
__global__ __launch_bounds__(128) void proj_kernel(
    const float* __restrict__ x,
    const float* __restrict__ lg, const float* __restrict__ lb,
    const float* __restrict__ Wk, const float* __restrict__ Wv)
{
    __shared__ float sA[64 * 68];        // 17408 B, fp32 LN'd rows, pitch 68
    __shared__ unsigned sW[64 * 68];     // 17408 B, bf16x2 [Wk|Wv], pitch 68 words
    const int tid = threadIdx.x;
    const int row0 = blockIdx.x * 64;

    // stage x tile (64x64 fp32) coalesced
    const float4* x4 = (const float4*)(x + (size_t)row0 * 64);
#pragma unroll
    for (int t = 0; t < 8; t++) {
        int F = t * 128 + tid;                 // float4 index within tile
        float4 vv = x4[F];
        *(float4*)&sA[(F >> 4) * 68 + (F & 15) * 4] = vv;
    }
    // stage W as bf16x2 words (word m of row k = cols 2m,2m+1)
#pragma unroll
    for (int t = 0; t < 16; t++) {
        int idx = t * 128 + tid;               // 2048 words per matrix
        int k = idx >> 5, m = idx & 31;
        float2 fk = *(const float2*)&Wk[k * 64 + 2 * m];
        float2 fv = *(const float2*)&Wv[k * 64 + 2 * m];
        sW[k * 68 + m]      = bf2(fk.x, fk.y);
        sW[k * 68 + 32 + m] = bf2(fv.x, fv.y);
    }
    __syncthreads();

    // layernorm rows in place: 4 warps x 16 rows, 2 elems/lane
    {
        int w = tid >> 5, l = tid & 31;
        float g0 = lg[2 * l], g1 = lg[2 * l + 1];
        float b0 = lb[2 * l], b1 = lb[2 * l + 1];
#pragma unroll
        for (int rr = 0; rr < 16; rr++) {
            int r = w * 16 + rr;
            float a0 = sA[r * 68 + 2 * l], a1 = sA[r * 68 + 2 * l + 1];
            float s = a0 + a1, s2 = a0 * a0 + a1 * a1;
#pragma unroll
            for (int o = 16; o; o >>= 1) {
                s  += __shfl_xor_sync(0xffffffffu, s, o);
                s2 += __shfl_xor_sync(0xffffffffu, s2, o);
            }
            float m = s * 0.015625f;
            float var = fmaxf(s2 * 0.015625f - m * m, 0.f);
            float inv = rsqrtf(var + 1e-5f);
            sA[r * 68 + 2 * l]     = (a0 - m) * inv * g0 + b0;
            sA[r * 68 + 2 * l + 1] = (a1 - m) * inv * g1 + b1;
        }
    }
    __syncthreads();

    const int tx = tid & 15, ty = tid >> 4;    // cols tx*8..+7, rows ty*8..+7
    unsigned long long acc[8][4];
#pragma unroll
    for (int j = 0; j < 8; j++)
#pragma unroll
        for (int m = 0; m < 4; m++) acc[j][m] = 0ull;

#pragma unroll 8
    for (int k = 0; k < 64; k++) {
        uint4 wv4 = *(const uint4*)&sW[k * 68 + tx * 4];
        unsigned long long w0 = bfpair(wv4.x);
        unsigned long long w1 = bfpair(wv4.y);
        unsigned long long w2 = bfpair(wv4.z);
        unsigned long long w3 = bfpair(wv4.w);
#pragma unroll
        for (int j = 0; j < 8; j++) {
            float a = sA[(ty * 8 + j) * 68 + k];
            unsigned long long aa = pk2(a, a);
            fma2(acc[j][0], aa, w0);
            fma2(acc[j][1], aa, w1);
            fma2(acc[j][2], aa, w2);
            fma2(acc[j][3], aa, w3);
        }
    }

    // store bf16x2: cols 0-63 -> g_k, 64-127 -> g_v
    unsigned* outp = (tx < 8) ? g_k : g_v;
    const int wbase = (tx < 8) ? tx * 4 : (tx - 8) * 4;
#pragma unroll
    for (int j = 0; j < 8; j++) {
        uint4 o;
        float2 f0 = upk2(acc[j][0]); o.x = bf2(f0.x, f0.y);
        float2 f1 = upk2(acc[j][1]); o.y = bf2(f1.x, f1.y);
        float2 f2 = upk2(acc[j][2]); o.z = bf2(f2.x, f2.y);
        float2 f3 = upk2(acc[j][3]); o.w = bf2(f3.x, f3.y);
        *(uint4*)&outp[(size_t)(row0 + ty * 8 + j) * 32 + wbase] = o;
    }
}

// ---------------- kernel 2: broadcast slots_init ----------------
__global__ void init_slots_kernel(const float* __restrict__ s0) {
    int i = blockIdx.x * blockDim.x + threadIdx.x;
    if (i < BB * SS * DD) g_slots[i] = s0[i % (SS * DD)];
}

// ---------------- kernel 3: LN(slots), q = sn@Wq * scale; zero accumulators ----
__global__ __launch_bounds__(64) void q_kernel(
    const float* __restrict__ lg, const float* __restrict__ lb,
    const float* __restrict__ Wq)
{
    const int blk = blockIdx.x;           // b*7 + s
    const int b = blk / SS, s = blk % SS;
    const int d = threadIdx.x;
    const int lane = d & 31, wid = d >> 5;

    float v = g_slots[blk * 64 + d];
    float s1 = v, s2 = v * v;
#pragma unroll
    for (int o = 16; o; o >>= 1) {
        s1 += __shfl_xor_sync(0xffffffffu, s1, o);
        s2 += __shfl_xor_sync(0xffffffffu, s2, o);
    }
    __shared__ float red[4];
    if (lane == 0) { red[wid] = s1; red[2 + wid] = s2; }
    __syncthreads();
    float S = red[0] + red[1], S2 = red[2] + red[3];
    float m = S * 0.015625f;
    float var = fmaxf(S2 * 0.015625f - m * m, 0.f);
    float inv = rsqrtf(var + 1e-5f);
    float sn = (v - m) * inv * lg[d] + lb[d];

    __shared__ float ssn[64];
    ssn[d] = sn;
    __syncthreads();

    float q = 0.f;
#pragma unroll 8
    for (int j = 0; j < 64; j++) q += ssn[j] * Wq[j * 64 + d];
    q *= 0.125f;

    g_qT[b * 512 + d * 8 + s] = q;
    if (s == 0) g_qT[b * 512 + d * 8 + 7] = 0.f;
    g_numer[blk * 64 + d] = 0.f;
    if (d == 0) g_denom[blk] = 0.f;
}

// ---------------- kernel 4: attention pass ----------------
// grid: (16 tiles, B), 256 threads = 8 warps. Each warp: one 32-row chunk.
__global__ __launch_bounds__(256) void attn_kernel() {
    const int b = blockIdx.y, tile = blockIdx.x;
    const int w = threadIdx.x >> 5, lane = threadIdx.x & 31;

    __shared__ float sQT[64 * 8];            // 2 KB
    __shared__ unsigned sK[8][32 * 33];      // 33.8 KB (bf16x2, pitch 33)
    __shared__ float sWt[8][32 * 8];         // 8 KB softmax weights
    __shared__ float sAcc[SS * 64];          // block numer accumulator
    __shared__ float sDen[SS];

    sQT[threadIdx.x]       = g_qT[b * 512 + threadIdx.x];
    sQT[256 + threadIdx.x] = g_qT[b * 512 + 256 + threadIdx.x];
    for (int i = threadIdx.x; i < SS * 64; i += 256) sAcc[i] = 0.f;
    if (threadIdx.x < SS) sDen[threadIdx.x] = 0.f;
    __syncthreads();

    const int chunkrow = tile * 256 + w * 32;
    const unsigned* kk = g_k + ((size_t)b * NN + chunkrow) * 32;
    unsigned* myK = sK[w];

#pragma unroll 8
    for (int r = 0; r < 32; r++)
        myK[r * 33 + lane] = kk[r * 32 + lane];
    __syncwarp();

    // phase 1: lane = row; 7 logits over 64 dims
    float p0 = 0, p1 = 0, p2 = 0, p3 = 0, p4 = 0, p5 = 0, p6 = 0;
    const unsigned* krow = myK + lane * 33;
#pragma unroll 8
    for (int j = 0; j < 32; j++) {
        unsigned kw = krow[j];
        float k0 = bflo(kw), k1 = bfhi(kw);
        float4 qa = *(float4*)&sQT[(2 * j) * 8];
        float4 qb = *(float4*)&sQT[(2 * j) * 8 + 4];
        float4 qc = *(float4*)&sQT[(2 * j + 1) * 8];
        float4 qd = *(float4*)&sQT[(2 * j + 1) * 8 + 4];
        p0 += k0 * qa.x + k1 * qc.x;
        p1 += k0 * qa.y + k1 * qc.y;
        p2 += k0 * qa.z + k1 * qc.z;
        p3 += k0 * qa.w + k1 * qc.w;
        p4 += k0 * qb.x + k1 * qd.x;
        p5 += k0 * qb.y + k1 * qd.y;
        p6 += k0 * qb.z + k1 * qd.z;
    }
    float mx = fmaxf(fmaxf(fmaxf(p0, p1), fmaxf(p2, p3)),
                     fmaxf(fmaxf(p4, p5), p6));
    float e0 = __expf(p0 - mx), e1 = __expf(p1 - mx), e2 = __expf(p2 - mx);
    float e3 = __expf(p3 - mx), e4 = __expf(p4 - mx), e5 = __expf(p5 - mx);
    float e6 = __expf(p6 - mx);
    float sum = e0 + e1 + e2 + e3 + e4 + e5 + e6;
    float inv = 1.f / sum;
    float ws[SS];
    ws[0] = e0 * inv + 1e-8f; ws[1] = e1 * inv + 1e-8f;
    ws[2] = e2 * inv + 1e-8f; ws[3] = e3 * inv + 1e-8f;
    ws[4] = e4 * inv + 1e-8f; ws[5] = e5 * inv + 1e-8f;
    ws[6] = e6 * inv + 1e-8f;
    float* wr = &sWt[w][lane * 8];
#pragma unroll
    for (int s = 0; s < SS; s++) wr[s] = ws[s];

    // denom: warp-reduce the 7 per-row weights
    float dsum[SS];
#pragma unroll
    for (int s = 0; s < SS; s++) {
        float t = ws[s];
#pragma unroll
        for (int o = 16; o; o >>= 1) t += __shfl_xor_sync(0xffffffffu, t, o);
        dsum[s] = t;
    }
    __syncwarp();

    // phase 2: lane = channel pair
    const unsigned* vv = g_v + ((size_t)b * NN + chunkrow) * 32;
    float nacc[14];
#pragma unroll
    for (int i = 0; i < 14; i++) nacc[i] = 0.f;
#pragma unroll 8
    for (int r = 0; r < 32; r++) {
        unsigned vw = vv[r * 32 + lane];
        float v0 = bflo(vw), v1 = bfhi(vw);
        float4 wa = *(float4*)&sWt[w][r * 8];
        float4 wb = *(float4*)&sWt[w][r * 8 + 4];
        nacc[0]  += wa.x * v0; nacc[1]  += wa.x * v1;
        nacc[2]  += wa.y * v0; nacc[3]  += wa.y * v1;
        nacc[4]  += wa.z * v0; nacc[5]  += wa.z * v1;
        nacc[6]  += wa.w * v0; nacc[7]  += wa.w * v1;
        nacc[8]  += wb.x * v0; nacc[9]  += wb.x * v1;
        nacc[10] += wb.y * v0; nacc[11] += wb.y * v1;
        nacc[12] += wb.z * v0; nacc[13] += wb.z * v1;
    }

    // block-level reduction in smem (stagger slot order by warp)
#pragma unroll
    for (int i = 0; i < SS; i++) {
        int s = (i + w) % SS;
        atomicAdd(&sAcc[s * 64 + 2 * lane],     nacc[2 * s]);
        atomicAdd(&sAcc[s * 64 + 2 * lane + 1], nacc[2 * s + 1]);
    }
    if (lane == 0) {
#pragma unroll
        for (int s = 0; s < SS; s++) atomicAdd(&sDen[s], dsum[s]);
    }
    __syncthreads();

    // drain to global
    float* np = g_numer + b * (SS * DD);
    for (int i = threadIdx.x; i < SS * 64; i += 256) atomicAdd(&np[i], sAcc[i]);
    if (threadIdx.x < SS) atomicAdd(&g_denom[b * SS + threadIdx.x], sDen[threadIdx.x]);
}

// ---------------- kernel 5: updates -> GRU -> MLP -> slots ----------------
// grid: B blocks of 448 threads (thread = s*64+d)
__global__ __launch_bounds__(448) void update_kernel(
    const float* __restrict__ wih, const float* __restrict__ whh,
    const float* __restrict__ bih, const float* __restrict__ bhh,
    const float* __restrict__ w1,  const float* __restrict__ b1v,
    const float* __restrict__ w2,  const float* __restrict__ b2v,
    float* __restrict__ out)
{
    const int b = blockIdx.x;
    const int tid = threadIdx.x;
    const int s = tid >> 6, d = tid & 63;
    const int blk = b * SS + s;

    __shared__ float su[SS][64], sh[SS][64], shn[SS][64], smm[SS][128];
    __shared__ float sWi[64 * 65], sWh[64 * 65];

    float den = g_denom[blk];
    float u = g_numer[blk * 64 + d] / den;
    float h = g_slots[blk * 64 + d];
    su[s][d] = u; sh[s][d] = h;

    float gi[3], gh[3];
    for (int gate = 0; gate < 3; gate++) {
        __syncthreads();
        for (int idx = tid; idx < 4096; idx += 448) {
            int rr = idx >> 6, cc = idx & 63;
            sWi[rr * 65 + cc] = wih[gate * 4096 + idx];
            sWh[rr * 65 + cc] = whh[gate * 4096 + idx];
        }
        __syncthreads();
        float a = bih[gate * 64 + d], c = bhh[gate * 64 + d];
#pragma unroll 8
        for (int t = 0; t < 64; t++) {
            a += su[s][t] * sWi[d * 65 + t];
            c += sh[s][t] * sWh[d * 65 + t];
        }
        gi[gate] = a; gh[gate] = c;
    }

    float r = 1.f / (1.f + __expf(-(gi[0] + gh[0])));
    float z = 1.f / (1.f + __expf(-(gi[1] + gh[1])));
    float n = tanhf(gi[2] + r * gh[2]);
    float hn = (1.f - z) * n + z * h;

    __syncthreads();
    shn[s][d] = hn;
    __syncthreads();

    float m0 = b1v[d], m1 = b1v[64 + d];
#pragma unroll 8
    for (int t = 0; t < 64; t++) {
        float ht = shn[s][t];
        m0 += ht * w1[t * 128 + d];
        m1 += ht * w1[t * 128 + 64 + d];
    }
    smm[s][d] = fmaxf(m0, 0.f);
    smm[s][64 + d] = fmaxf(m1, 0.f);
    __syncthreads();

    float o = hn + b2v[d];
#pragma unroll 8
    for (int c = 0; c < 128; c++) o += smm[s][c] * w2[c * 64 + d];

    g_slots[blk * 64 + d] = o;
    if (out) out[blk * 64 + d] = o;
}

// ---------------- launch ----------------
extern "C" void kernel_launch(void* const* d_in, const int* in_sizes, int n_in,
                              void* d_out, int out_size) {
    (void)in_sizes; (void)n_in; (void)out_size;
    const float* x          = (const float*)d_in[0];
    const float* ln_inp_g   = (const float*)d_in[1];
    const float* ln_inp_b   = (const float*)d_in[2];
    const float* ln_slot_g  = (const float*)d_in[3];
    const float* ln_slot_b  = (const float*)d_in[4];
    const float* slots_init = (const float*)d_in[5];
    const float* Wk         = (const float*)d_in[6];
    const float* Wv         = (const float*)d_in[7];
    const float* Wq         = (const float*)d_in[8];
    const float* gwih       = (const float*)d_in[9];
    const float* gwhh       = (const float*)d_in[10];
    const float* gbih       = (const float*)d_in[11];
    const float* gbhh       = (const float*)d_in[12];
    const float* w1         = (const float*)d_in[13];
    const float* b1         = (const float*)d_in[14];
    const float* w2         = (const float*)d_in[15];
    const float* b2         = (const float*)d_in[16];
    float* out = (float*)d_out;

    proj_kernel<<<(BB * NN) / 64, 128>>>(x, ln_inp_g, ln_inp_b, Wk, Wv);
    init_slots_kernel<<<(BB * SS * DD + 255) / 256, 256>>>(slots_init);
    for (int it = 0; it < 3; it++) {
        q_kernel<<<BB * SS, 64>>>(ln_slot_g, ln_slot_b, Wq);
        attn_kernel<<<dim3(16, BB), 256>>>();
        update_kernel<<<BB, 448>>>(gwih, gwhh, gbih, gbhh,
                                   w1, b1, w2, b2, it == 2 ? out : nullptr);
    }
}

// round 4
// speedup vs baseline: 1.5383x; 1.0749x over previous
#include <cuda_runtime.h>
#include <cstdint>

#define BB 64
#define NN 4096
#define SS 7

// ---------------- scratch (static device globals; no allocation) ----------------
__device__ unsigned g_k[BB * NN * 32];       // bf16x2 words: 32 MB
__device__ unsigned g_v[BB * NN * 32];       // 32 MB
__device__ float g_qT[BB * 64 * 8];          // q transposed [b][d][s] (pad 8)
__device__ float g_slots[BB * SS * 64];
__device__ float g_numer[BB * SS * 64];
__device__ float g_denom[BB * SS];
__device__ unsigned g_Bt[128 * 32];          // B^T: [n][k] bf16x2 words, n=0..127 (Wk|Wv)
__device__ float g_wihT[64 * 192];           // GRU weights transposed [t][j]
__device__ float g_whhT[64 * 192];

// ---------------- helpers ----------------
__device__ __forceinline__ unsigned bf2(float lo, float hi) {
    unsigned r;
    asm("cvt.rn.bf16x2.f32 %0, %1, %2;" : "=r"(r) : "f"(hi), "f"(lo));
    return r;
}
__device__ __forceinline__ float bflo(unsigned w) { return __uint_as_float(w << 16); }
__device__ __forceinline__ float bfhi(unsigned w) { return __uint_as_float(w & 0xffff0000u); }

__device__ __forceinline__ void mma_bf16(float& c0, float& c1, float& c2, float& c3,
                                         unsigned a0, unsigned a1, unsigned a2, unsigned a3,
                                         unsigned b0, unsigned b1) {
    asm volatile(
        "mma.sync.aligned.m16n8k16.row.col.f32.bf16.bf16.f32 "
        "{%0,%1,%2,%3}, {%4,%5,%6,%7}, {%8,%9}, {%0,%1,%2,%3};"
        : "+f"(c0), "+f"(c1), "+f"(c2), "+f"(c3)
        : "r"(a0), "r"(a1), "r"(a2), "r"(a3), "r"(b0), "r"(b1));
}

// ---------------- kernel 0: one-time prep (B^T, GRU transposes, slots) ----------
__global__ void init_kernel(const float* __restrict__ s0,
                            const float* __restrict__ Wk, const float* __restrict__ Wv,
                            const float* __restrict__ wih, const float* __restrict__ whh) {
    int i = blockIdx.x * blockDim.x + threadIdx.x;
    if (i < BB * SS * 64) g_slots[i] = s0[i % (SS * 64)];
    if (i < 4096) {
        int n = i >> 5, w = i & 31;
        const float* W = (n < 64) ? Wk : Wv;
        int nc = n & 63;
        float lo = W[(2 * w) * 64 + nc];
        float hi = W[(2 * w + 1) * 64 + nc];
        g_Bt[i] = bf2(lo, hi);
    }
    if (i < 12288) {
        int t = i / 192, j = i % 192;
        g_wihT[i] = wih[j * 64 + t];
        g_whhT[i] = whh[j * 64 + t];
    }
}

// ---------------- kernel 1: fused LN + bf16 HMMA GEMM -> k|v ---------------------
// grid: 2048 blocks (128 rows), 256 threads = 8 warps (16 rows each).
#define PITCH 36   // words per row (72 bf16) -> conflict-free fragment loads
__global__ __launch_bounds__(256) void proj_kernel(
    const float* __restrict__ x,
    const float* __restrict__ lg, const float* __restrict__ lb)
{
    __shared__ unsigned sA[128 * PITCH];   // LN'd rows, bf16x2, [row][kword]
    __shared__ unsigned sB[128 * PITCH];   // B^T, bf16x2, [n][kword]

    const int tid = threadIdx.x;
    const int w = tid >> 5, lane = tid & 31;
    const int row0 = blockIdx.x * 128;

    // stage B^T (L2-hot after first wave)
#pragma unroll
    for (int t = 0; t < 16; t++) {
        int idx = t * 256 + tid;
        sB[(idx >> 5) * PITCH + (idx & 31)] = g_Bt[idx];
    }

    // LN: 2 threads per row (half each), bf16 convert into sA
    {
        const int r = tid >> 1, half = tid & 1;
        const float4* g4 = (const float4*)(lg + half * 32);
        const float4* b4 = (const float4*)(lb + half * 32);
        const float4* xr = (const float4*)(x + ((size_t)(row0 + r)) * 64 + half * 32);
        float4 f[8];
#pragma unroll
        for (int q = 0; q < 8; q++) f[q] = xr[q];
        float s1 = 0.f, s2 = 0.f;
#pragma unroll
        for (int q = 0; q < 8; q++) {
            s1 += f[q].x + f[q].y + f[q].z + f[q].w;
            s2 += f[q].x * f[q].x + f[q].y * f[q].y + f[q].z * f[q].z + f[q].w * f[q].w;
        }
        s1 += __shfl_xor_sync(0xffffffffu, s1, 1);
        s2 += __shfl_xor_sync(0xffffffffu, s2, 1);
        float m = s1 * 0.015625f;
        float var = fmaxf(s2 * 0.015625f - m * m, 0.f);
        float inv = rsqrtf(var + 1e-5f);
#pragma unroll
        for (int q = 0; q < 8; q++) {
            float4 gg = g4[q], bb = b4[q];
            float y0 = (f[q].x - m) * inv * gg.x + bb.x;
            float y1 = (f[q].y - m) * inv * gg.y + bb.y;
            float y2 = (f[q].z - m) * inv * gg.z + bb.z;
            float y3 = (f[q].w - m) * inv * gg.w + bb.w;
            int mw = half * 16 + q * 2;
            sA[r * PITCH + mw]     = bf2(y0, y1);
            sA[r * PITCH + mw + 1] = bf2(y2, y3);
        }
    }
    __syncthreads();

    // warp = 16 rows [r0, r0+16). Fragment rows: ra = r0 + lane/4, rb = ra + 8.
    const int r0 = w * 16;
    const int qr = lane >> 2, qc = lane & 3;
    const int ra = r0 + qr, rb = ra + 8;

    // preload A fragments for all 4 k-steps (k0 word = qc + kstep*8; +4 for cols+8)
    unsigned afr[4][4];
#pragma unroll
    for (int ks = 0; ks < 4; ks++) {
        afr[ks][0] = sA[ra * PITCH + qc + ks * 8];
        afr[ks][1] = sA[rb * PITCH + qc + ks * 8];
        afr[ks][2] = sA[ra * PITCH + qc + 4 + ks * 8];
        afr[ks][3] = sA[rb * PITCH + qc + 4 + ks * 8];
    }

    const size_t growa = (size_t)(row0 + ra), growb = (size_t)(row0 + rb);
#pragma unroll
    for (int blk = 0; blk < 16; blk++) {
        float c0 = 0.f, c1 = 0.f, c2 = 0.f, c3 = 0.f;
        const int n = blk * 8 + qr;
#pragma unroll
        for (int ks = 0; ks < 4; ks++) {
            unsigned b0 = sB[n * PITCH + qc + ks * 8];
            unsigned b1 = sB[n * PITCH + qc + 4 + ks * 8];
            mma_bf16(c0, c1, c2, c3, afr[ks][0], afr[ks][1], afr[ks][2], afr[ks][3], b0, b1);
        }
        unsigned* dst = (blk < 8) ? g_k : g_v;
        const int widx = (blk & 7) * 4 + qc;
        dst[growa * 32 + widx] = bf2(c0, c1);
        dst[growb * 32 + widx] = bf2(c2, c3);
    }
}

// ---------------- kernel 3: LN(slots), q = sn@Wq * scale; zero accumulators ----
__global__ __launch_bounds__(64) void q_kernel(
    const float* __restrict__ lg, const float* __restrict__ lb,
    const float* __restrict__ Wq)
{
    const int blk = blockIdx.x;           // b*7 + s
    const int b = blk / SS, s = blk % SS;
    const int d = threadIdx.x;
    const int lane = d & 31, wid = d >> 5;

    float v = g_slots[blk * 64 + d];
    float s1 = v, s2 = v * v;
#pragma unroll
    for (int o = 16; o; o >>= 1) {
        s1 += __shfl_xor_sync(0xffffffffu, s1, o);
        s2 += __shfl_xor_sync(0xffffffffu, s2, o);
    }
    __shared__ float red[4];
    if (lane == 0) { red[wid] = s1; red[2 + wid] = s2; }
    __syncthreads();
    float S = red[0] + red[1], S2 = red[2] + red[3];
    float m = S * 0.015625f;
    float var = fmaxf(S2 * 0.015625f - m * m, 0.f);
    float inv = rsqrtf(var + 1e-5f);
    float sn = (v - m) * inv * lg[d] + lb[d];

    __shared__ float ssn[64];
    ssn[d] = sn;
    __syncthreads();

    float q = 0.f;
#pragma unroll 8
    for (int j = 0; j < 64; j++) q += ssn[j] * Wq[j * 64 + d];
    q *= 0.125f;

    g_qT[b * 512 + d * 8 + s] = q;
    if (s == 0) g_qT[b * 512 + d * 8 + 7] = 0.f;
    g_numer[blk * 64 + d] = 0.f;
    if (d == 0) g_denom[blk] = 0.f;
}

// ---------------- kernel 4: attention pass ----------------
// grid: (16 tiles, B), 256 threads = 8 warps; warp = one 32-row chunk.
__global__ __launch_bounds__(256) void attn_kernel() {
    const int b = blockIdx.y, tile = blockIdx.x;
    const int w = threadIdx.x >> 5, lane = threadIdx.x & 31;

    __shared__ float sQT[512];               // 2 KB: q [d][8]
    __shared__ float sWt[8][256];            // 8 KB: softmax weights [row][8]
    __shared__ __align__(16) unsigned sK[8][1056];   // 33.8 KB; later overlaid by partials

    sQT[threadIdx.x]       = g_qT[b * 512 + threadIdx.x];
    sQT[256 + threadIdx.x] = g_qT[b * 512 + 256 + threadIdx.x];
    __syncthreads();

    const int chunkrow = tile * 256 + w * 32;
    const unsigned* kk = g_k + ((size_t)b * NN + chunkrow) * 32;
    unsigned* myK = sK[w];
#pragma unroll 8
    for (int r = 0; r < 32; r++)
        myK[r * 33 + lane] = kk[r * 32 + lane];
    __syncwarp();

    // phase 1: lane = row; 7 logits over 64 dims
    float p0 = 0, p1 = 0, p2 = 0, p3 = 0, p4 = 0, p5 = 0, p6 = 0;
    const unsigned* krow = myK + lane * 33;
#pragma unroll 8
    for (int j = 0; j < 32; j++) {
        unsigned kw = krow[j];
        float k0 = bflo(kw), k1 = bfhi(kw);
        float4 qa = *(float4*)&sQT[(2 * j) * 8];
        float4 qb = *(float4*)&sQT[(2 * j) * 8 + 4];
        float4 qc = *(float4*)&sQT[(2 * j + 1) * 8];
        float4 qd = *(float4*)&sQT[(2 * j + 1) * 8 + 4];
        p0 += k0 * qa.x + k1 * qc.x;
        p1 += k0 * qa.y + k1 * qc.y;
        p2 += k0 * qa.z + k1 * qc.z;
        p3 += k0 * qa.w + k1 * qc.w;
        p4 += k0 * qb.x + k1 * qd.x;
        p5 += k0 * qb.y + k1 * qd.y;
        p6 += k0 * qb.z + k1 * qd.z;
    }
    float mx = fmaxf(fmaxf(fmaxf(p0, p1), fmaxf(p2, p3)),
                     fmaxf(fmaxf(p4, p5), p6));
    float e0 = __expf(p0 - mx), e1 = __expf(p1 - mx), e2 = __expf(p2 - mx);
    float e3 = __expf(p3 - mx), e4 = __expf(p4 - mx), e5 = __expf(p5 - mx);
    float e6 = __expf(p6 - mx);
    float sum = e0 + e1 + e2 + e3 + e4 + e5 + e6;
    float inv = 1.f / sum;
    float ws[SS];
    ws[0] = e0 * inv + 1e-8f; ws[1] = e1 * inv + 1e-8f;
    ws[2] = e2 * inv + 1e-8f; ws[3] = e3 * inv + 1e-8f;
    ws[4] = e4 * inv + 1e-8f; ws[5] = e5 * inv + 1e-8f;
    ws[6] = e6 * inv + 1e-8f;
    float* wr = &sWt[w][lane * 8];
#pragma unroll
    for (int s = 0; s < SS; s++) wr[s] = ws[s];

    float dsum[SS];
#pragma unroll
    for (int s = 0; s < SS; s++) {
        float t = ws[s];
#pragma unroll
        for (int o = 16; o; o >>= 1) t += __shfl_xor_sync(0xffffffffu, t, o);
        dsum[s] = t;
    }
    __syncwarp();

    // phase 2: lane = channel pair
    const unsigned* vv = g_v + ((size_t)b * NN + chunkrow) * 32;
    float nacc[14];
#pragma unroll
    for (int i = 0; i < 14; i++) nacc[i] = 0.f;
#pragma unroll 8
    for (int r = 0; r < 32; r++) {
        unsigned vw = vv[r * 32 + lane];
        float v0 = bflo(vw), v1 = bfhi(vw);
        float4 wa = *(float4*)&sWt[w][r * 8];
        float4 wb = *(float4*)&sWt[w][r * 8 + 4];
        nacc[0]  += wa.x * v0; nacc[1]  += wa.x * v1;
        nacc[2]  += wa.y * v0; nacc[3]  += wa.y * v1;
        nacc[4]  += wa.z * v0; nacc[5]  += wa.z * v1;
        nacc[6]  += wa.w * v0; nacc[7]  += wa.w * v1;
        nacc[8]  += wb.x * v0; nacc[9]  += wb.x * v1;
        nacc[10] += wb.y * v0; nacc[11] += wb.y * v1;
        nacc[12] += wb.z * v0; nacc[13] += wb.z * v1;
    }
    __syncwarp();

    // write per-warp partials into this warp's (now-dead) K region
    float* red = (float*)&sK[w][0];
#pragma unroll
    for (int s = 0; s < SS; s++) {
        red[s * 64 + 2 * lane]     = nacc[2 * s];
        red[s * 64 + 2 * lane + 1] = nacc[2 * s + 1];
    }
    if (lane == 0) {
#pragma unroll
        for (int s = 0; s < SS; s++) red[448 + s] = dsum[s];
    }
    __syncthreads();

    // tree-reduce 8 warps, drain with global atomics (16 blocks per b)
    float* np = g_numer + b * (SS * 64);
    for (int i = threadIdx.x; i < 455; i += 256) {
        float t = 0.f;
#pragma unroll
        for (int w2 = 0; w2 < 8; w2++) t += ((float*)&sK[w2][0])[i];
        if (i < 448) atomicAdd(&np[i], t);
        else atomicAdd(&g_denom[b * SS + (i - 448)], t);
    }
}

// ---------------- kernel 5: updates -> GRU -> MLP -> slots ----------------
// grid: B blocks of 448 threads (thread = s*64+d); transposed GRU weights direct.
__global__ __launch_bounds__(448) void update_kernel(
    const float* __restrict__ bih, const float* __restrict__ bhh,
    const float* __restrict__ w1,  const float* __restrict__ b1v,
    const float* __restrict__ w2,  const float* __restrict__ b2v,
    float* __restrict__ out)
{
    const int b = blockIdx.x;
    const int tid = threadIdx.x;
    const int s = tid >> 6, d = tid & 63;
    const int blk = b * SS + s;

    __shared__ float su[SS][64], sh[SS][64], shn[SS][64], smm[SS][128];

    float den = g_denom[blk];
    float u = g_numer[blk * 64 + d] / den;
    float h = g_slots[blk * 64 + d];
    su[s][d] = u; sh[s][d] = h;
    __syncthreads();

    float a0 = bih[d], a1 = bih[64 + d], a2 = bih[128 + d];
    float c0 = bhh[d], c1 = bhh[64 + d], c2 = bhh[128 + d];
#pragma unroll 4
    for (int t = 0; t < 64; t++) {
        float ut = su[s][t], ht = sh[s][t];
        const float* wi = &g_wihT[t * 192];
        const float* wh = &g_whhT[t * 192];
        a0 += ut * wi[d]; a1 += ut * wi[64 + d]; a2 += ut * wi[128 + d];
        c0 += ht * wh[d]; c1 += ht * wh[64 + d]; c2 += ht * wh[128 + d];
    }

    float r = 1.f / (1.f + __expf(-(a0 + c0)));
    float z = 1.f / (1.f + __expf(-(a1 + c1)));
    float n = tanhf(a2 + r * c2);
    float hn = (1.f - z) * n + z * h;

    shn[s][d] = hn;
    __syncthreads();

    float m0 = b1v[d], m1 = b1v[64 + d];
#pragma unroll 8
    for (int t = 0; t < 64; t++) {
        float ht = shn[s][t];
        m0 += ht * w1[t * 128 + d];
        m1 += ht * w1[t * 128 + 64 + d];
    }
    smm[s][d] = fmaxf(m0, 0.f);
    smm[s][64 + d] = fmaxf(m1, 0.f);
    __syncthreads();

    float o = hn + b2v[d];
#pragma unroll 8
    for (int c = 0; c < 128; c++) o += smm[s][c] * w2[c * 64 + d];

    g_slots[blk * 64 + d] = o;
    if (out) out[blk * 64 + d] = o;
}

// ---------------- launch ----------------
extern "C" void kernel_launch(void* const* d_in, const int* in_sizes, int n_in,
                              void* d_out, int out_size) {
    (void)in_sizes; (void)n_in; (void)out_size;
    const float* x          = (const float*)d_in[0];
    const float* ln_inp_g   = (const float*)d_in[1];
    const float* ln_inp_b   = (const float*)d_in[2];
    const float* ln_slot_g  = (const float*)d_in[3];
    const float* ln_slot_b  = (const float*)d_in[4];
    const float* slots_init = (const float*)d_in[5];
    const float* Wk         = (const float*)d_in[6];
    const float* Wv         = (const float*)d_in[7];
    const float* Wq         = (const float*)d_in[8];
    const float* gwih       = (const float*)d_in[9];
    const float* gwhh       = (const float*)d_in[10];
    const float* gbih       = (const float*)d_in[11];
    const float* gbhh       = (const float*)d_in[12];
    const float* w1         = (const float*)d_in[13];
    const float* b1         = (const float*)d_in[14];
    const float* w2         = (const float*)d_in[15];
    const float* b2         = (const float*)d_in[16];
    float* out = (float*)d_out;

    init_kernel<<<112, 256>>>(slots_init, Wk, Wv, gwih, gwhh);
    proj_kernel<<<(BB * NN) / 128, 256>>>(x, ln_inp_g, ln_inp_b);
    for (int it = 0; it < 3; it++) {
        q_kernel<<<BB * SS, 64>>>(ln_slot_g, ln_slot_b, Wq);
        attn_kernel<<<dim3(16, BB), 256>>>();
        update_kernel<<<BB, 448>>>(gbih, gbhh, w1, b1, w2, b2, it == 2 ? out : nullptr);
    }
}